// round 3
// baseline (speedup 1.0000x reference)
#include <cuda_runtime.h>
#include <math.h>

#define CC 128
#define MID 8
#define SB 32      // blocks per spatial dim
#define SPD 64     // full spatial dim

#define TWO_SQRT2 2.8284271247461903f

// scratch (allocation-free rule: __device__ globals)
__device__ float g_part[2 * CC * SB * SB];        // per-(b,c,d,h) corner partials (1 MB)
__device__ float g_gmod[2 * CC];                  // global-MLP output
__device__ float g_loc[2 * CC * SB * SB * SB];    // local-MLP logits, pre-sigmoid (33.5 MB)

// ---------------------------------------------------------------------------
// Kernel 1: single corner pass per (b,d,h):
//   - load 128ch x 32w corners (x_sum = 2*sqrt(2)*corner)
//   - emit per-channel partial sums for gap (deterministic structure)
//   - local MLP -> pre-sigmoid logits to g_loc
// ---------------------------------------------------------------------------
__global__ __launch_bounds__(256) void k1_corner(const float* __restrict__ x,
                                                 const float* __restrict__ lw1,
                                                 const float* __restrict__ lb1,
                                                 const float* __restrict__ lw2,
                                                 const float* __restrict__ lb2) {
    int bid = blockIdx.x;          // 0..2047
    int b = bid >> 10;
    int d = (bid >> 5) & 31;
    int h = bid & 31;
    int t = threadIdx.x;

    __shared__ float s_s[CC][SB + 1];   // padded: conflict-free column sums
    __shared__ float s_hid[MID][SB];
    __shared__ float s_lw1[MID * CC];
    __shared__ float s_lw2[CC * MID];
    __shared__ float s_lb2[CC];

    for (int i = t; i < MID * CC; i += 256) s_lw1[i] = lw1[i];
    for (int i = t; i < CC * MID; i += 256) s_lw2[i] = lw2[i];
    if (t < CC) s_lb2[t] = lb2[t];

    const float* xb = x + (size_t)b * CC * SPD * SPD * SPD;

    // strided corner loads: 128 channels x 32 w-blocks
    for (int i = t; i < CC * SB; i += 256) {
        int c = i >> 5;
        int w = i & 31;
        s_s[c][w] = TWO_SQRT2 *
            xb[(((size_t)c * SPD + 2 * d) * SPD + 2 * h) * SPD + 2 * w];
    }
    __syncthreads();

    // gap partials: threads 0..127, one channel each (padded smem: no conflicts)
    if (t < CC) {
        float s = 0.f;
        #pragma unroll 8
        for (int w = 0; w < SB; w++) s += s_s[t][w];
        // layout [b][c][d*32+h] so k2 reads contiguous
        g_part[((size_t)(b * CC + t) << 10) + (d << 5) + h] = s;
    }

    // hidden layer: exactly 256 (m,w) pairs
    {
        int m = t >> 5;
        int w = t & 31;
        float a = lb1[m];
        const float* wrow = &s_lw1[m * CC];
        #pragma unroll 8
        for (int c = 0; c < CC; c++) a += wrow[c] * s_s[c][w];
        s_hid[m][w] = fmaxf(a, 0.f);
    }
    __syncthreads();

    // local logits (pre-sigmoid, no global term) -> g_loc [bc][d][h][w]
    float* lout = g_loc + (((size_t)(b * CC) * SB + d) * SB + h) * SB;
    for (int i = t; i < CC * SB; i += 256) {
        int c = i >> 5;
        int w = i & 31;
        float a = s_lb2[c];
        #pragma unroll
        for (int m = 0; m < MID; m++) a += s_lw2[c * MID + m] * s_hid[m][w];
        lout[(size_t)c * (SB * SB * SB) + w] = a;
    }
}

// ---------------------------------------------------------------------------
// Kernel 2: reduce gap partials (deterministic tree) + global MLP.
// one CTA per batch, 1024 threads.
// ---------------------------------------------------------------------------
__global__ __launch_bounds__(1024) void k2_gmlp(const float* __restrict__ gw1,
                                                const float* __restrict__ gb1,
                                                const float* __restrict__ gw2,
                                                const float* __restrict__ gb2) {
    int b = blockIdx.x;
    int t = threadIdx.x;       // 0..1023
    int c = t >> 3;            // 0..127
    int q = t & 7;             // 0..7

    __shared__ float s_red[CC][8];
    __shared__ float gap_s[CC];
    __shared__ float hid[MID];

    // each thread sums 128 contiguous floats (32 float4)
    {
        const float4* p = (const float4*)(g_part + ((size_t)(b * CC + c) << 10) + (q << 7));
        float s = 0.f;
        #pragma unroll 8
        for (int i = 0; i < 32; i++) {
            float4 v = p[i];
            s += (v.x + v.y) + (v.z + v.w);
        }
        s_red[c][q] = s;
    }
    __syncthreads();

    if (t < CC) {
        float s = 0.f;
        #pragma unroll
        for (int i = 0; i < 8; i++) s += s_red[t][i];
        gap_s[t] = s * (1.0f / 32768.0f);
    }
    __syncthreads();

    if (t < MID) {
        float a = gb1[t];
        #pragma unroll 8
        for (int cc = 0; cc < CC; cc++) a += gw1[t * CC + cc] * gap_s[cc];
        hid[t] = fmaxf(a, 0.f);
    }
    __syncthreads();

    if (t < CC) {
        float a = gb2[t];
        #pragma unroll
        for (int m = 0; m < MID; m++) a += gw2[t * MID + m] * hid[m];
        g_gmod[b * CC + t] = a;
    }
}

// ---------------------------------------------------------------------------
// Kernel 3: pure streaming blend. One thread = 2 adjacent 2x2x2 blocks.
// gate = sigmoid(g_gmod[bc] + local_logit);  out = gate*x + (1-gate)*block_mean
// ---------------------------------------------------------------------------
__global__ __launch_bounds__(256) void k3_blend(const float* __restrict__ x,
                                                float* __restrict__ out) {
    unsigned tid = blockIdx.x * 256u + threadIdx.x;   // 0 .. 4194303
    int w4 = tid & 15;            // float4 index along w
    int h  = (tid >> 4) & 31;
    int d  = (tid >> 9) & 31;
    int bc = tid >> 14;           // 0..255

    size_t base = ((size_t)bc * SPD + 2 * d) * (SPD * SPD)
                + (size_t)(2 * h) * SPD + 4 * w4;

    float4 r00 = __ldcs((const float4*)(x + base));
    float4 r01 = __ldcs((const float4*)(x + base + SPD));
    float4 r10 = __ldcs((const float4*)(x + base + SPD * SPD));
    float4 r11 = __ldcs((const float4*)(x + base + SPD * SPD + SPD));

    float2 lg = *(const float2*)(g_loc + (((size_t)bc * SB + d) * SB + h) * SB + 2 * w4);
    float gg = __ldg(&g_gmod[bc]);
    float g0 = 1.0f / (1.0f + __expf(-(gg + lg.x)));
    float g1 = 1.0f / (1.0f + __expf(-(gg + lg.y)));

    float m0 = (r00.x + r00.y + r01.x + r01.y + r10.x + r10.y + r11.x + r11.y) * 0.125f;
    float m1 = (r00.z + r00.w + r01.z + r01.w + r10.z + r10.w + r11.z + r11.w) * 0.125f;
    float om0 = (1.0f - g0) * m0;
    float om1 = (1.0f - g1) * m1;

    r00.x = fmaf(g0, r00.x, om0); r00.y = fmaf(g0, r00.y, om0);
    r01.x = fmaf(g0, r01.x, om0); r01.y = fmaf(g0, r01.y, om0);
    r10.x = fmaf(g0, r10.x, om0); r10.y = fmaf(g0, r10.y, om0);
    r11.x = fmaf(g0, r11.x, om0); r11.y = fmaf(g0, r11.y, om0);
    r00.z = fmaf(g1, r00.z, om1); r00.w = fmaf(g1, r00.w, om1);
    r01.z = fmaf(g1, r01.z, om1); r01.w = fmaf(g1, r01.w, om1);
    r10.z = fmaf(g1, r10.z, om1); r10.w = fmaf(g1, r10.w, om1);
    r11.z = fmaf(g1, r11.z, om1); r11.w = fmaf(g1, r11.w, om1);

    __stcs((float4*)(out + base),                   r00);
    __stcs((float4*)(out + base + SPD),             r01);
    __stcs((float4*)(out + base + SPD * SPD),       r10);
    __stcs((float4*)(out + base + SPD * SPD + SPD), r11);
}

// ---------------------------------------------------------------------------
extern "C" void kernel_launch(void* const* d_in, const int* in_sizes, int n_in,
                              void* d_out, int out_size) {
    const float* x   = (const float*)d_in[0];
    const float* gw1 = (const float*)d_in[1];
    const float* gb1 = (const float*)d_in[2];
    const float* gw2 = (const float*)d_in[3];
    const float* gb2 = (const float*)d_in[4];
    const float* lw1 = (const float*)d_in[5];
    const float* lb1 = (const float*)d_in[6];
    const float* lw2 = (const float*)d_in[7];
    const float* lb2 = (const float*)d_in[8];
    float* out = (float*)d_out;

    k1_corner<<<2 * SB * SB, 256>>>(x, lw1, lb1, lw2, lb2);
    k2_gmlp<<<2, 1024>>>(gw1, gb1, gw2, gb2);
    k3_blend<<<16384, 256>>>(x, out);
}

// round 4
// speedup vs baseline: 1.3081x; 1.3081x over previous
#include <cuda_runtime.h>
#include <math.h>

#define CC 128
#define MID 8
#define SB 32      // blocks per spatial dim
#define SPD 64     // full spatial dim

#define TWO_SQRT2 2.8284271247461903f

// scratch (allocation-free rule: __device__ globals)
__device__ float g_part[2 * CC * 4];   // 4 partial corner sums per (b,c)
__device__ float g_gmod[2 * CC];       // global-MLP output

// ---------------------------------------------------------------------------
// Kernel 1: corner partial sums, fully coalesced float4 reads.
// grid = 1024: (bc 0..255) x (slice 0..3); each CTA sums 8 d-blocks of corners.
// Also warms L2 with the corner lines k_main's prologue re-reads.
// ---------------------------------------------------------------------------
__global__ __launch_bounds__(256) void k_gap(const float* __restrict__ x) {
    int bc    = blockIdx.x >> 2;     // 0..255
    int slice = blockIdx.x & 3;      // 0..3
    int t = threadIdx.x;

    const float* base = x + (size_t)bc * (SPD * SPD * SPD)
                          + (size_t)(16 * slice) * SPD * SPD;  // z = 2*(8*slice)

    // 256 rows (8 d-blocks x 32 h), 16 float4 per row; thread = (row16, col)
    int col = t & 15;
    int r0  = t >> 4;               // 0..15
    float sum = 0.f;
    #pragma unroll
    for (int iter = 0; iter < 16; iter++) {
        int row = iter * 16 + r0;   // 0..255
        int dblk = row >> 5;        // 0..7
        int h    = row & 31;
        const float4 v = *(const float4*)(base
            + (size_t)(2 * dblk) * SPD * SPD + (size_t)(2 * h) * SPD + 4 * col);
        sum += v.x + v.z;           // even-w elements = corners
    }
    __shared__ float red[256];
    red[t] = sum;
    __syncthreads();
    for (int s = 128; s > 0; s >>= 1) {
        if (t < s) red[t] += red[t + s];
        __syncthreads();
    }
    if (t == 0) g_part[bc * 4 + slice] = red[0];
}

// ---------------------------------------------------------------------------
// Kernel 2: reduce 4 partials -> gap, then global MLP -> g_gmod. Tiny.
// ---------------------------------------------------------------------------
__global__ __launch_bounds__(128) void k_gmlp(const float* __restrict__ gw1,
                                              const float* __restrict__ gb1,
                                              const float* __restrict__ gw2,
                                              const float* __restrict__ gb2) {
    int b = blockIdx.x;
    int t = threadIdx.x;  // 0..127
    __shared__ float gap_s[CC];
    __shared__ float hid[MID];
    {
        const float4 p = *(const float4*)(g_part + (b * CC + t) * 4);
        gap_s[t] = (p.x + p.y + p.z + p.w) * (TWO_SQRT2 / 32768.0f);
    }
    __syncthreads();
    if (t < MID) {
        float a = gb1[t];
        #pragma unroll 8
        for (int c = 0; c < CC; c++) a += gw1[t * CC + c] * gap_s[c];
        hid[t] = fmaxf(a, 0.f);
    }
    __syncthreads();
    float a = gb2[t];
    #pragma unroll
    for (int m = 0; m < MID; m++) a += gw2[t * MID + m] * hid[m];
    g_gmod[b * CC + t] = a;
}

// ---------------------------------------------------------------------------
// Kernel 3: fused gate + blend. CTA = (b, d-block, h-block).
// Phase 1: float4 corner loads (warm lines, reused by phase 3) -> smem.
// Phase 2: hidden layer (256 (m,w) pairs).
// Phase 3: per-thread inline gate (sigmoid) + streaming blend of 2x2x2 blocks.
// ---------------------------------------------------------------------------
__global__ __launch_bounds__(256) void k_main(const float* __restrict__ x,
                                              const float* __restrict__ lw1,
                                              const float* __restrict__ lb1,
                                              const float* __restrict__ lw2,
                                              const float* __restrict__ lb2,
                                              float* __restrict__ out) {
    int bid = blockIdx.x;          // 0..2047
    int b = bid >> 10;
    int d = (bid >> 5) & 31;
    int h = bid & 31;
    int t = threadIdx.x;

    __shared__ float s_s[CC][SB];      // raw corner values (16 KB)
    __shared__ float s_hid[MID][SB];   // 1 KB
    __shared__ float s_lw1[MID * CC];  // 4 KB (pre-scaled by 2*sqrt2)
    __shared__ float s_lw2[CC * MID];  // 4 KB
    __shared__ float s_gl[CC];         // gmod + lb2 combined

    // weights (fold the 2*sqrt(2) x_sum scale into lw1)
    for (int i = t; i < MID * CC; i += 256) s_lw1[i] = TWO_SQRT2 * lw1[i];
    for (int i = t; i < CC * MID; i += 256) s_lw2[i] = lw2[i];
    if (t < CC) s_gl[t] = g_gmod[b * CC + t] + lb2[t];

    const float* xb = x + (size_t)b * CC * SPD * SPD * SPD;
    const size_t row_off = (size_t)(2 * d) * SPD * SPD + (size_t)(2 * h) * SPD;

    // phase 1: corner rows via float4 (likely L2 hits from k_gap)
    {
        int col = t & 15;            // float4 column
        int c0  = t >> 4;            // 0..15
        #pragma unroll
        for (int iter = 0; iter < 8; iter++) {
            int c = iter * 16 + c0;
            float4 v = *(const float4*)(xb + (size_t)c * (SPD * SPD * SPD) + row_off + 4 * col);
            s_s[c][2 * col]     = v.x;
            s_s[c][2 * col + 1] = v.z;
        }
    }
    __syncthreads();

    // phase 2: hidden layer; exactly 256 (m,w) pairs
    {
        int m = t >> 5;
        int w = t & 31;
        float a = lb1[m];
        const float* wrow = &s_lw1[m * CC];
        #pragma unroll 8
        for (int c = 0; c < CC; c++) a += wrow[c] * s_s[c][w];
        s_hid[m][w] = fmaxf(a, 0.f);
    }
    __syncthreads();

    // phase 3: inline gates + streaming blend
    float* ob = out + (size_t)b * CC * SPD * SPD * SPD;
    int w4   = t & 15;               // float4 index along w
    int csub = t >> 4;               // 0..15
    #pragma unroll 1
    for (int cg = 0; cg < CC; cg += 16) {
        int c = cg + csub;

        // gates for the two 2x2x2 blocks this thread's float4 spans
        float a0 = s_gl[c], a1 = s_gl[c];
        const float* w2row = &s_lw2[c * MID];
        #pragma unroll
        for (int m = 0; m < MID; m++) {
            a0 = fmaf(w2row[m], s_hid[m][2 * w4],     a0);
            a1 = fmaf(w2row[m], s_hid[m][2 * w4 + 1], a1);
        }
        float g0 = 1.0f / (1.0f + __expf(-a0));
        float g1 = 1.0f / (1.0f + __expf(-a1));

        size_t base = (size_t)c * (SPD * SPD * SPD) + row_off + 4 * w4;
        float4 r00 = *(const float4*)(xb + base);                    // corner row: L1 hit
        float4 r01 = __ldcs((const float4*)(xb + base + SPD));
        float4 r10 = __ldcs((const float4*)(xb + base + SPD * SPD));
        float4 r11 = __ldcs((const float4*)(xb + base + SPD * SPD + SPD));

        float m0 = (r00.x + r00.y + r01.x + r01.y + r10.x + r10.y + r11.x + r11.y) * 0.125f;
        float m1 = (r00.z + r00.w + r01.z + r01.w + r10.z + r10.w + r11.z + r11.w) * 0.125f;
        float om0 = (1.0f - g0) * m0;
        float om1 = (1.0f - g1) * m1;

        r00.x = fmaf(g0, r00.x, om0); r00.y = fmaf(g0, r00.y, om0);
        r01.x = fmaf(g0, r01.x, om0); r01.y = fmaf(g0, r01.y, om0);
        r10.x = fmaf(g0, r10.x, om0); r10.y = fmaf(g0, r10.y, om0);
        r11.x = fmaf(g0, r11.x, om0); r11.y = fmaf(g0, r11.y, om0);
        r00.z = fmaf(g1, r00.z, om1); r00.w = fmaf(g1, r00.w, om1);
        r01.z = fmaf(g1, r01.z, om1); r01.w = fmaf(g1, r01.w, om1);
        r10.z = fmaf(g1, r10.z, om1); r10.w = fmaf(g1, r10.w, om1);
        r11.z = fmaf(g1, r11.z, om1); r11.w = fmaf(g1, r11.w, om1);

        __stcs((float4*)(ob + base),                   r00);
        __stcs((float4*)(ob + base + SPD),             r01);
        __stcs((float4*)(ob + base + SPD * SPD),       r10);
        __stcs((float4*)(ob + base + SPD * SPD + SPD), r11);
    }
}

// ---------------------------------------------------------------------------
extern "C" void kernel_launch(void* const* d_in, const int* in_sizes, int n_in,
                              void* d_out, int out_size) {
    const float* x   = (const float*)d_in[0];
    const float* gw1 = (const float*)d_in[1];
    const float* gb1 = (const float*)d_in[2];
    const float* gw2 = (const float*)d_in[3];
    const float* gb2 = (const float*)d_in[4];
    const float* lw1 = (const float*)d_in[5];
    const float* lb1 = (const float*)d_in[6];
    const float* lw2 = (const float*)d_in[7];
    const float* lb2 = (const float*)d_in[8];
    float* out = (float*)d_out;

    k_gap<<<1024, 256>>>(x);
    k_gmlp<<<2, 128>>>(gw1, gb1, gw2, gb2);
    k_main<<<2 * SB * SB, 256>>>(x, lw1, lb1, lw2, lb2, out);
}

// round 5
// speedup vs baseline: 1.3570x; 1.0374x over previous
#include <cuda_runtime.h>
#include <math.h>

#define CC 128
#define MID 8
#define SB 32      // blocks per spatial dim
#define SPD 64     // full spatial dim

#define TWO_SQRT2 2.8284271247461903f

// scratch (allocation-free rule: __device__ globals)
__device__ float g_part[2 * CC * 1024];            // [b][c][d*32+h] raw corner sums (1 MB)
__device__ float g_gap[2 * CC];                    // reduced gap
__device__ float g_gmod[2 * CC];                   // global-MLP output
__device__ float g_hid[2 * 1024 * MID * SB];       // [tile][m][w] hidden acts (2 MB)

// ---------------------------------------------------------------------------
// Kernel A: single corner pass per (b,d,h) tile:
//   float4 corner loads -> smem; per-channel w-sums -> g_part;
//   hidden layer (2*sqrt2 folded into lw1) -> g_hid.
// ---------------------------------------------------------------------------
__global__ __launch_bounds__(256) void kA(const float* __restrict__ x,
                                          const float* __restrict__ lw1,
                                          const float* __restrict__ lb1) {
    int bid = blockIdx.x;          // tile = b*1024 + d*32 + h
    int b = bid >> 10;
    int d = (bid >> 5) & 31;
    int h = bid & 31;
    int t = threadIdx.x;

    __shared__ float s_s[CC][SB + 1];   // raw corners, padded (conflict-free col reads)
    __shared__ float s_lw1[MID * CC];   // pre-scaled by 2*sqrt2

    for (int i = t; i < MID * CC; i += 256) s_lw1[i] = TWO_SQRT2 * lw1[i];

    const float* xb = x + (size_t)b * CC * SPD * SPD * SPD;
    const size_t row_off = (size_t)(2 * d) * SPD * SPD + (size_t)(2 * h) * SPD;

    {
        int col = t & 15;            // float4 column
        int c0  = t >> 4;
        #pragma unroll
        for (int it = 0; it < 8; it++) {
            int c = it * 16 + c0;
            float4 v = *(const float4*)(xb + (size_t)c * (SPD * SPD * SPD) + row_off + 4 * col);
            s_s[c][2 * col]     = v.x;
            s_s[c][2 * col + 1] = v.z;
        }
    }
    __syncthreads();

    // gap partial: one channel per thread (banks: (c*33+w)%32 — conflict-free)
    if (t < CC) {
        float s = 0.f;
        #pragma unroll 8
        for (int w = 0; w < SB; w++) s += s_s[t][w];
        g_part[((size_t)(b * CC + t) << 10) + (d << 5) + h] = s;
    }

    // hidden layer: exactly 256 (m,w) pairs
    {
        int m = t >> 5;
        int w = t & 31;
        float a = lb1[m];
        const float* wrow = &s_lw1[m * CC];
        #pragma unroll 8
        for (int c = 0; c < CC; c++) a = fmaf(wrow[c], s_s[c][w], a);
        g_hid[((size_t)bid * MID + m) * SB + w] = fmaxf(a, 0.f);
    }
}

// ---------------------------------------------------------------------------
// Kernel B: per-(b,c) reduction of 1024 contiguous partials -> gap. 256 CTAs.
// ---------------------------------------------------------------------------
__global__ __launch_bounds__(256) void kRed() {
    int bc = blockIdx.x;
    int t  = threadIdx.x;
    const float4 v = ((const float4*)(g_part + ((size_t)bc << 10)))[t];
    float s = (v.x + v.y) + (v.z + v.w);
    #pragma unroll
    for (int o = 16; o > 0; o >>= 1) s += __shfl_down_sync(0xffffffffu, s, o);
    __shared__ float red[8];
    if ((t & 31) == 0) red[t >> 5] = s;
    __syncthreads();
    if (t == 0) {
        float tot = 0.f;
        #pragma unroll
        for (int i = 0; i < 8; i++) tot += red[i];
        g_gap[bc] = tot * (TWO_SQRT2 / 32768.0f);
    }
}

// ---------------------------------------------------------------------------
// Kernel C: global MLP -> g_gmod. 2 CTAs x 128 threads.
// ---------------------------------------------------------------------------
__global__ __launch_bounds__(128) void kMLP(const float* __restrict__ gw1,
                                            const float* __restrict__ gb1,
                                            const float* __restrict__ gw2,
                                            const float* __restrict__ gb2) {
    int b = blockIdx.x;
    int t = threadIdx.x;
    __shared__ float gap_s[CC];
    __shared__ float hid[MID];
    gap_s[t] = g_gap[b * CC + t];
    __syncthreads();
    if (t < MID) {
        float a = gb1[t];
        #pragma unroll 8
        for (int c = 0; c < CC; c++) a = fmaf(gw1[t * CC + c], gap_s[c], a);
        hid[t] = fmaxf(a, 0.f);
    }
    __syncthreads();
    float a = gb2[t];
    #pragma unroll
    for (int m = 0; m < MID; m++) a = fmaf(gw2[t * MID + m], hid[m], a);
    g_gmod[b * CC + t] = a;
}

// ---------------------------------------------------------------------------
// Kernel D: pure streaming blend with inline gate.
// tid -> (bc, d, h, w4); gate = sigmoid(gmod[bc] + lb2 + lw2·hid[tile][:, w]).
// ---------------------------------------------------------------------------
__global__ __launch_bounds__(256) void kBlend(const float* __restrict__ x,
                                              const float* __restrict__ lw2,
                                              const float* __restrict__ lb2,
                                              float* __restrict__ out) {
    unsigned tid = blockIdx.x * 256u + threadIdx.x;   // 0 .. 4194303
    int w4 = tid & 15;
    int h  = (tid >> 4) & 31;
    int d  = (tid >> 9) & 31;
    int bc = tid >> 14;            // 0..255
    int c  = bc & 127;

    // gate logits from hidden activations (2MB buffer: L2 hits)
    size_t tile = ((size_t)(bc >> 7) << 10) + (d << 5) + h;
    const float* hb = g_hid + tile * (MID * SB) + 2 * w4;
    float gl = g_gmod[bc] + __ldg(&lb2[c]);
    float a0 = gl, a1 = gl;
    #pragma unroll
    for (int m = 0; m < MID; m++) {
        float2 hv = *(const float2*)(hb + m * SB);
        float wm = __ldg(&lw2[c * MID + m]);
        a0 = fmaf(wm, hv.x, a0);
        a1 = fmaf(wm, hv.y, a1);
    }
    float g0 = 1.0f / (1.0f + __expf(-a0));
    float g1 = 1.0f / (1.0f + __expf(-a1));

    size_t base = ((size_t)bc * SPD + 2 * d) * (SPD * SPD)
                + (size_t)(2 * h) * SPD + 4 * w4;

    float4 r00 = __ldcs((const float4*)(x + base));
    float4 r01 = __ldcs((const float4*)(x + base + SPD));
    float4 r10 = __ldcs((const float4*)(x + base + SPD * SPD));
    float4 r11 = __ldcs((const float4*)(x + base + SPD * SPD + SPD));

    float m0 = (r00.x + r00.y + r01.x + r01.y + r10.x + r10.y + r11.x + r11.y) * 0.125f;
    float m1 = (r00.z + r00.w + r01.z + r01.w + r10.z + r10.w + r11.z + r11.w) * 0.125f;
    float om0 = (1.0f - g0) * m0;
    float om1 = (1.0f - g1) * m1;

    r00.x = fmaf(g0, r00.x, om0); r00.y = fmaf(g0, r00.y, om0);
    r01.x = fmaf(g0, r01.x, om0); r01.y = fmaf(g0, r01.y, om0);
    r10.x = fmaf(g0, r10.x, om0); r10.y = fmaf(g0, r10.y, om0);
    r11.x = fmaf(g0, r11.x, om0); r11.y = fmaf(g0, r11.y, om0);
    r00.z = fmaf(g1, r00.z, om1); r00.w = fmaf(g1, r00.w, om1);
    r01.z = fmaf(g1, r01.z, om1); r01.w = fmaf(g1, r01.w, om1);
    r10.z = fmaf(g1, r10.z, om1); r10.w = fmaf(g1, r10.w, om1);
    r11.z = fmaf(g1, r11.z, om1); r11.w = fmaf(g1, r11.w, om1);

    __stcs((float4*)(out + base),                   r00);
    __stcs((float4*)(out + base + SPD),             r01);
    __stcs((float4*)(out + base + SPD * SPD),       r10);
    __stcs((float4*)(out + base + SPD * SPD + SPD), r11);
}

// ---------------------------------------------------------------------------
extern "C" void kernel_launch(void* const* d_in, const int* in_sizes, int n_in,
                              void* d_out, int out_size) {
    const float* x   = (const float*)d_in[0];
    const float* gw1 = (const float*)d_in[1];
    const float* gb1 = (const float*)d_in[2];
    const float* gw2 = (const float*)d_in[3];
    const float* gb2 = (const float*)d_in[4];
    const float* lw1 = (const float*)d_in[5];
    const float* lb1 = (const float*)d_in[6];
    const float* lw2 = (const float*)d_in[7];
    const float* lb2 = (const float*)d_in[8];
    float* out = (float*)d_out;

    kA<<<2048, 256>>>(x, lw1, lb1);
    kRed<<<256, 256>>>();
    kMLP<<<2, 128>>>(gw1, gb1, gw2, gb2);
    kBlend<<<16384, 256>>>(x, lw2, lb2, out);
}